// round 16
// baseline (speedup 1.0000x reference)
#include <cuda_runtime.h>
#include <cuda_bf16.h>
#include <cstdint>

// Fixed shapes
#define H_DIM   1024
#define N_DIM   64
#define SEQ_L   2048
// Per-h GEMM (J=32 split):  l = 32c + j,  c = 0..63, j = 0..31
//   A[c, 2n] = Re(Ct2 * r^(32c)),  A[c, 2n+1] = Im(...)     (64 x 128) fp16
//   B[2n, j] = Re(r^j),            B[2n+1, j] = -Im(r^j)    (stored [j][kappa]) fp16
// Single-pass fp16 MMA (m16n8k16), f32 accumulate.
// TWO h per block, double-buffered: MMA(h0) || gen(h1), STG(h0) || MMA(h1).

// SMEM: two A/B tile buffers + param arrays (128 float2 each: h0 then h1)
#define BUF0       0          // A0 @0 (16KB), B0 @16384 (8KB)
#define BUF1       24576      // A1, B1
#define AB_B_OFF   16384      // B offset within a buffer
#define P_CT       49152
#define P_R        50176
#define P_R4       51200
#define P_R8       52224
#define P_R16      53248
#define P_RHO      54272
#define P_RHO8     55296
#define SMEM_BYTES 56320      // 55KB -> 4 CTAs/SM, grid 512 = 1 resident wave

__device__ __forceinline__ uint32_t smem_u32(const void* p) {
    uint32_t a;
    asm("{ .reg .u64 t; cvta.to.shared.u64 t, %1; cvt.u32.u64 %0, t; }" : "=r"(a) : "l"(p));
    return a;
}
__device__ __forceinline__ uint32_t cvt_f16x2(float hi_f, float lo_f) {
    uint32_t r;
    asm("cvt.rn.f16x2.f32 %0, %1, %2;" : "=r"(r) : "f"(hi_f), "f"(lo_f));
    return r;
}
__device__ __forceinline__ float2 cmul(float2 a, float2 b) {
    return make_float2(a.x * b.x - a.y * b.y, a.x * b.y + a.y * b.x);
}
__device__ __forceinline__ float2 csqr(float2 a) {
    return make_float2(a.x * a.x - a.y * a.y, 2.0f * a.x * a.y);
}
__device__ __forceinline__ void ldsm4(uint32_t* r, uint32_t addr) {
    asm volatile("ldmatrix.sync.aligned.m8n8.x4.shared.b16 {%0,%1,%2,%3}, [%4];"
                 : "=r"(r[0]), "=r"(r[1]), "=r"(r[2]), "=r"(r[3]) : "r"(addr));
}
__device__ __forceinline__ void mma_f16(float* d, const uint32_t* a,
                                        uint32_t b0, uint32_t b1) {
    asm volatile(
        "mma.sync.aligned.m16n8k16.row.col.f32.f16.f16.f32 "
        "{%0,%1,%2,%3}, {%4,%5,%6,%7}, {%8,%9}, {%0,%1,%2,%3};"
        : "+f"(d[0]), "+f"(d[1]), "+f"(d[2]), "+f"(d[3])
        : "r"(a[0]), "r"(a[1]), "r"(a[2]), "r"(a[3]), "r"(b0), "r"(b1));
}
__device__ __forceinline__ void sts64(uint32_t addr, uint32_t w0, uint32_t w1) {
    asm volatile("st.shared.v2.b32 [%0], {%1, %2};" :: "r"(addr), "r"(w0), "r"(w1)
                 : "memory");
}

// Generate A/B fp16 tiles for one h into buffer `buf` using params slot `hsel`.
__device__ __forceinline__ void gen_tiles(char* sm, uint32_t sbase,
                                          uint32_t buf, int hsel, int tx)
{
    const int np = tx & 31;                 // n pair: n0 = 2np, n1 = 2np+1
    const int q8 = tx >> 5;                 // row group 0..7
    const uint32_t pb = (uint32_t)(hsel * 512 + np * 16);

    float4 ctv   = *(const float4*)(sm + P_CT   + pb);
    float4 rv    = *(const float4*)(sm + P_R    + pb);
    float4 r4v   = *(const float4*)(sm + P_R4   + pb);
    float4 r8v   = *(const float4*)(sm + P_R8   + pb);
    float4 r16v  = *(const float4*)(sm + P_R16  + pb);
    float4 rhov  = *(const float4*)(sm + P_RHO  + pb);
    float4 rho8v = *(const float4*)(sm + P_RHO8 + pb);

    const float2 r0   = make_float2(rv.x, rv.y),     r1   = make_float2(rv.z, rv.w);
    const float2 rho0 = make_float2(rhov.x, rhov.y), rho1 = make_float2(rhov.z, rhov.w);
    const uint32_t colb = (uint32_t)np * 8u;

    // ---- B rows j = 4*q8 .. +3 : (Re r^j, -Im r^j) ----
    {
        float2 v0 = make_float2(1.0f, 0.0f), v1 = v0;
        if (q8 & 1) { v0 = make_float2(r4v.x, r4v.y);  v1 = make_float2(r4v.z, r4v.w); }
        if (q8 & 2) { v0 = cmul(v0, make_float2(r8v.x, r8v.y));
                      v1 = cmul(v1, make_float2(r8v.z, r8v.w)); }
        if (q8 & 4) { v0 = cmul(v0, make_float2(r16v.x, r16v.y));
                      v1 = cmul(v1, make_float2(r16v.z, r16v.w)); }
#pragma unroll
        for (int i = 0; i < 4; i++) {
            int j = 4 * q8 + i;
            uint32_t addr = sbase + buf + AB_B_OFF + (uint32_t)j * 256u
                          + (colb ^ (((uint32_t)(j & 7)) << 4));
            sts64(addr, cvt_f16x2(-v0.y, v0.x), cvt_f16x2(-v1.y, v1.x));
            v0 = cmul(v0, r0);
            v1 = cmul(v1, r1);
        }
    }

    // ---- A rows c = 8*q8 .. +7 : W = Ct2 * rho^c ----
    {
        float2 rho8_0  = make_float2(rho8v.x, rho8v.y);
        float2 rho8_1  = make_float2(rho8v.z, rho8v.w);
        float2 rho16_0 = csqr(rho8_0),  rho16_1 = csqr(rho8_1);
        float2 rho32_0 = csqr(rho16_0), rho32_1 = csqr(rho16_1);

        float2 w0 = make_float2(1.0f, 0.0f), w1 = w0;
        if (q8 & 1) { w0 = rho8_0;  w1 = rho8_1; }
        if (q8 & 2) { w0 = cmul(w0, rho16_0); w1 = cmul(w1, rho16_1); }
        if (q8 & 4) { w0 = cmul(w0, rho32_0); w1 = cmul(w1, rho32_1); }
        w0 = cmul(w0, make_float2(ctv.x, ctv.y));
        w1 = cmul(w1, make_float2(ctv.z, ctv.w));
#pragma unroll
        for (int i = 0; i < 8; i++) {
            int c = 8 * q8 + i;
            uint32_t addr = sbase + buf + (uint32_t)c * 256u
                          + (colb ^ (((uint32_t)i) << 4));      // c&7 == i
            sts64(addr, cvt_f16x2(w0.y, w0.x), cvt_f16x2(w1.y, w1.x));
            w0 = cmul(w0, rho0);
            w1 = cmul(w1, rho1);
        }
    }
}

// Run the per-warp GEMM over one buffer; accumulate into d[2][4].
__device__ __forceinline__ void mma_tiles(float d[2][4], uint32_t sbase,
                                          uint32_t buf, int tx)
{
    const int wid = tx >> 5;
    const int lid = tx & 31;
    const int mt  = wid & 3;
    const int nh  = wid >> 2;

    const uint32_t lrow = (uint32_t)(lid & 15);
    const uint32_t c16  = (uint32_t)(lid & 16);
    const uint32_t swz  = (lrow & 7u) << 4;
    const uint32_t a_rowb = sbase + buf + ((uint32_t)(mt * 16) + lrow) * 256u;
    const uint32_t b_rowb = sbase + buf + AB_B_OFF
                          + ((uint32_t)(nh * 16) + lrow) * 256u;

#pragma unroll
    for (int kt = 0; kt < 8; kt++) {
        const uint32_t col = ((uint32_t)(kt * 32) + c16) ^ swz;
        uint32_t a[4], b[4];
        ldsm4(a, a_rowb + col);
        ldsm4(b, b_rowb + col);        // m0/m1: nt0/nt1 (k lo), m2/m3: (k hi)
        mma_f16(d[0], a, b[0], b[2]);
        mma_f16(d[1], a, b[1], b[3]);
    }
}

__device__ __forceinline__ void store_out(const float d[2][4], float* outh, int tx)
{
    const int wid = tx >> 5;
    const int lid = tx & 31;
    const int mt  = wid & 3;
    const int nh  = wid >> 2;
    const int row = mt * 16 + (lid >> 2);
    const int jb  = nh * 16 + 2 * (lid & 3);
#pragma unroll
    for (int nt = 0; nt < 2; nt++) {
        *reinterpret_cast<float2*>(outh + 32 * row + jb + 8 * nt) =
            make_float2(d[nt][0], d[nt][1]);
        *reinterpret_cast<float2*>(outh + 32 * (row + 8) + jb + 8 * nt) =
            make_float2(d[nt][2], d[nt][3]);
    }
}

__global__ void __launch_bounds__(256, 4) ssk_hmma(
    const float* __restrict__ Cri, const float* __restrict__ logdt,
    const float* __restrict__ Bri, const float* __restrict__ invAr,
    const float* __restrict__ Aim, float* __restrict__ out)
{
    extern __shared__ __align__(1024) char sm[];
    const int tx = threadIdx.x;
    const int h0 = blockIdx.x * 2;
    const uint32_t sbase = smem_u32(sm);

    // ===== Phase 0: params for BOTH h (128 threads; h1 LDG latency hoisted) =====
    if (tx < 128) {
        const int hsel = tx >> 6;
        const int n    = tx & 63;
        const int idx  = (h0 + hsel) * N_DIM + n;

        float cr = Cri[2 * idx], ci = Cri[2 * idx + 1];
        float br = Bri[2 * idx], bi = Bri[2 * idx + 1];
        float dt = __expf(logdt[h0 + hsel]);
        float Ar = -__expf(invAr[idx]);
        float Ai = Aim[idx];

        float zr = Ar * dt, zi = Ai * dt;
        float dr = 1.0f - 0.5f * zr, di = -0.5f * zi;
        float inv = __fdividef(1.0f, dr * dr + di * di);

        float bcr = br * cr - bi * ci;
        float bci = br * ci + bi * cr;
        float s = 2.0f * dt * inv;
        float2 ct = make_float2((bcr * dr + bci * di) * s,     // Ct2 = 2*B*C*dt/den
                                (bci * dr - bcr * di) * s);

        float nr = 1.0f + 0.5f * zr, ni = 0.5f * zi;
        float2 r = make_float2((nr * dr + ni * di) * inv,      // r, |r| < 1
                               (ni * dr - nr * di) * inv);

        float2 r2   = csqr(r);
        float2 r4   = csqr(r2);
        float2 r8   = csqr(r4);
        float2 r16  = csqr(r8);
        float2 rho  = csqr(r16);     // r^32
        float2 t64  = csqr(rho);
        float2 t128 = csqr(t64);
        float2 rho8 = csqr(t128);    // r^256 = rho^8

        const int slot = hsel * 64 + n;
        ((float2*)(sm + P_CT))[slot]   = ct;
        ((float2*)(sm + P_R))[slot]    = r;
        ((float2*)(sm + P_R4))[slot]   = r4;
        ((float2*)(sm + P_R8))[slot]   = r8;
        ((float2*)(sm + P_R16))[slot]  = r16;
        ((float2*)(sm + P_RHO))[slot]  = rho;
        ((float2*)(sm + P_RHO8))[slot] = rho8;
    }
    __syncthreads();

    // ===== gen h0 =====
    gen_tiles(sm, sbase, BUF0, 0, tx);
    __syncthreads();

    // ===== MMA(h0)  ||  gen(h1) — independent streams =====
    float d0[2][4];
#pragma unroll
    for (int nt = 0; nt < 2; nt++)
#pragma unroll
        for (int i = 0; i < 4; i++) d0[nt][i] = 0.0f;
    mma_tiles(d0, sbase, BUF0, tx);
    gen_tiles(sm, sbase, BUF1, 1, tx);
    __syncthreads();

    // ===== STG(h0)  ||  MMA(h1) =====
    store_out(d0, out + (size_t)h0 * SEQ_L, tx);
    float d1[2][4];
#pragma unroll
    for (int nt = 0; nt < 2; nt++)
#pragma unroll
        for (int i = 0; i < 4; i++) d1[nt][i] = 0.0f;
    mma_tiles(d1, sbase, BUF1, tx);
    store_out(d1, out + (size_t)(h0 + 1) * SEQ_L, tx);
}

extern "C" void kernel_launch(void* const* d_in, const int* in_sizes, int n_in,
                              void* d_out, int out_size)
{
    const float* Cri   = (const float*)d_in[0];   // (1, H, N, 2)
    const float* logdt = (const float*)d_in[1];   // (H,)
    const float* Bri   = (const float*)d_in[2];   // (H, N, 2)  (n_ssm == H)
    const float* invAr = (const float*)d_in[3];   // (H, N)
    const float* Aim   = (const float*)d_in[4];   // (H, N)
    float* out = (float*)d_out;                   // (1, H, L)

    cudaFuncSetAttribute(ssk_hmma, cudaFuncAttributeMaxDynamicSharedMemorySize,
                         SMEM_BYTES);
    ssk_hmma<<<H_DIM / 2, 256, SMEM_BYTES>>>(Cri, logdt, Bri, invAr, Aim, out);
}

// round 17
// speedup vs baseline: 1.0239x; 1.0239x over previous
#include <cuda_runtime.h>
#include <cuda_bf16.h>
#include <cstdint>

// Fixed shapes
#define H_DIM   1024
#define N_DIM   64
#define SEQ_L   2048
// Per-h GEMM (J=32 split):  l = 32c + j,  c = 0..63, j = 0..31
//   A[c, 2n] = Re(Ct2 * r^(32c)),  A[c, 2n+1] = Im(...)     (64 x 128) fp16
//   B[2n, j] = Re(r^j),            B[2n+1, j] = -Im(r^j)    (stored [j][kappa]) fp16
// Single-pass fp16 MMA (m16n8k16), f32 accumulate.
// Sized for 8 CTAs/SM: regs<=32 (launch_bounds), smem 26.5KB.

// SMEM: A/B tiles row-major 256B rows, XOR-swizzle in 16B units by (row&7)<<4.
#define A_OFF      0        // 64 x 256B = 16384
#define B_OFF      16384    // 32 x 256B = 8192
#define P_CT       24576    // 5 param arrays x 64 float2 = 2560B
#define P_R        25088
#define P_R4       25600
#define P_R8       26112
#define P_RHO      26624
#define SMEM_BYTES 27136    // 26.5KB

__device__ __forceinline__ uint32_t smem_u32(const void* p) {
    uint32_t a;
    asm("{ .reg .u64 t; cvta.to.shared.u64 t, %1; cvt.u32.u64 %0, t; }" : "=r"(a) : "l"(p));
    return a;
}
__device__ __forceinline__ uint32_t cvt_f16x2(float hi_f, float lo_f) {
    uint32_t r;
    asm("cvt.rn.f16x2.f32 %0, %1, %2;" : "=r"(r) : "f"(hi_f), "f"(lo_f));
    return r;
}
__device__ __forceinline__ float2 cmul(float2 a, float2 b) {
    return make_float2(a.x * b.x - a.y * b.y, a.x * b.y + a.y * b.x);
}
__device__ __forceinline__ float2 csqr(float2 a) {
    return make_float2(a.x * a.x - a.y * a.y, 2.0f * a.x * a.y);
}
__device__ __forceinline__ void ldsm4(uint32_t* r, uint32_t addr) {
    asm volatile("ldmatrix.sync.aligned.m8n8.x4.shared.b16 {%0,%1,%2,%3}, [%4];"
                 : "=r"(r[0]), "=r"(r[1]), "=r"(r[2]), "=r"(r[3]) : "r"(addr));
}
__device__ __forceinline__ void mma_f16(float* d, const uint32_t* a,
                                        uint32_t b0, uint32_t b1) {
    asm volatile(
        "mma.sync.aligned.m16n8k16.row.col.f32.f16.f16.f32 "
        "{%0,%1,%2,%3}, {%4,%5,%6,%7}, {%8,%9}, {%0,%1,%2,%3};"
        : "+f"(d[0]), "+f"(d[1]), "+f"(d[2]), "+f"(d[3])
        : "r"(a[0]), "r"(a[1]), "r"(a[2]), "r"(a[3]), "r"(b0), "r"(b1));
}
__device__ __forceinline__ void sts64(uint32_t addr, uint32_t w0, uint32_t w1) {
    asm volatile("st.shared.v2.b32 [%0], {%1, %2};" :: "r"(addr), "r"(w0), "r"(w1)
                 : "memory");
}

__global__ void __launch_bounds__(256, 8) ssk_hmma(
    const float* __restrict__ Cri, const float* __restrict__ logdt,
    const float* __restrict__ Bri, const float* __restrict__ invAr,
    const float* __restrict__ Aim, float* __restrict__ out)
{
    extern __shared__ __align__(1024) char sm[];
    const int tx = threadIdx.x;
    const int h  = blockIdx.x;
    const uint32_t sbase = smem_u32(sm);

    // ========== Phase 0: per-n params (64 threads, deduped) ==========
    if (tx < 64) {
        const int n   = tx;
        const int idx = h * N_DIM + n;

        float cr = Cri[2 * idx], ci = Cri[2 * idx + 1];
        float br = Bri[2 * idx], bi = Bri[2 * idx + 1];
        float dt = __expf(logdt[h]);
        float Ar = -__expf(invAr[idx]);
        float Ai = Aim[idx];

        float zr = Ar * dt, zi = Ai * dt;
        float dr = 1.0f - 0.5f * zr, di = -0.5f * zi;
        float inv = __fdividef(1.0f, dr * dr + di * di);

        float bcr = br * cr - bi * ci;
        float bci = br * ci + bi * cr;
        float s = 2.0f * dt * inv;
        float2 ct = make_float2((bcr * dr + bci * di) * s,    // Ct2 = 2*B*C*dt/den
                                (bci * dr - bcr * di) * s);

        float nr = 1.0f + 0.5f * zr, ni = 0.5f * zi;
        float2 r = make_float2((nr * dr + ni * di) * inv,     // r, |r| < 1
                               (ni * dr - nr * di) * inv);

        float2 r2  = csqr(r);
        float2 r4  = csqr(r2);
        float2 r8  = csqr(r4);
        float2 r16 = csqr(r8);
        float2 rho = csqr(r16);      // r^32

        ((float2*)(sm + P_CT))[n]  = ct;
        ((float2*)(sm + P_R))[n]   = r;
        ((float2*)(sm + P_R4))[n]  = r4;
        ((float2*)(sm + P_R8))[n]  = r8;
        ((float2*)(sm + P_RHO))[n] = rho;
    }
    __syncthreads();

    // ========== Phase 1: tile generation (256 threads = 32 n-pairs x 8 q) ====
    {
        const int np = tx & 31;                 // n pair: n0 = 2np, n1 = 2np+1
        const int q8 = tx >> 5;                 // row group 0..7
        const uint32_t pb = (uint32_t)np * 16u; // byte offset of float2 pair

        float4 ctv  = *(const float4*)(sm + P_CT  + pb);
        float4 rv   = *(const float4*)(sm + P_R   + pb);
        float4 r4v  = *(const float4*)(sm + P_R4  + pb);
        float4 r8v  = *(const float4*)(sm + P_R8  + pb);
        float4 rhov = *(const float4*)(sm + P_RHO + pb);

        const float2 r0   = make_float2(rv.x, rv.y),     r1   = make_float2(rv.z, rv.w);
        const float2 rho0 = make_float2(rhov.x, rhov.y), rho1 = make_float2(rhov.z, rhov.w);
        const uint32_t colb = (uint32_t)np * 8u;

        // ---- B rows j = 4*q8 .. +3 : (Re r^j, -Im r^j) ----
        {
            float2 r16_0 = csqr(make_float2(r8v.x, r8v.y));
            float2 r16_1 = csqr(make_float2(r8v.z, r8v.w));
            float2 v0 = make_float2(1.0f, 0.0f), v1 = v0;
            if (q8 & 1) { v0 = make_float2(r4v.x, r4v.y);  v1 = make_float2(r4v.z, r4v.w); }
            if (q8 & 2) { v0 = cmul(v0, make_float2(r8v.x, r8v.y));
                          v1 = cmul(v1, make_float2(r8v.z, r8v.w)); }
            if (q8 & 4) { v0 = cmul(v0, r16_0);
                          v1 = cmul(v1, r16_1); }
#pragma unroll
            for (int i = 0; i < 4; i++) {
                int j = 4 * q8 + i;
                uint32_t addr = sbase + B_OFF + (uint32_t)j * 256u
                              + (colb ^ (((uint32_t)(j & 7)) << 4));
                sts64(addr, cvt_f16x2(-v0.y, v0.x), cvt_f16x2(-v1.y, v1.x));
                v0 = cmul(v0, r0);
                v1 = cmul(v1, r1);
            }
        }

        // ---- A rows c = 8*q8 .. +7 : W = Ct2 * rho^c ----
        {
            float2 rho8_0  = csqr(csqr(csqr(rho0)));
            float2 rho8_1  = csqr(csqr(csqr(rho1)));
            float2 rho16_0 = csqr(rho8_0),  rho16_1 = csqr(rho8_1);
            float2 rho32_0 = csqr(rho16_0), rho32_1 = csqr(rho16_1);

            float2 w0 = make_float2(1.0f, 0.0f), w1 = w0;
            if (q8 & 1) { w0 = rho8_0;  w1 = rho8_1; }
            if (q8 & 2) { w0 = cmul(w0, rho16_0); w1 = cmul(w1, rho16_1); }
            if (q8 & 4) { w0 = cmul(w0, rho32_0); w1 = cmul(w1, rho32_1); }
            w0 = cmul(w0, make_float2(ctv.x, ctv.y));
            w1 = cmul(w1, make_float2(ctv.z, ctv.w));
#pragma unroll
            for (int i = 0; i < 8; i++) {
                int c = 8 * q8 + i;
                uint32_t addr = sbase + A_OFF + (uint32_t)c * 256u
                              + (colb ^ (((uint32_t)i) << 4));     // c&7 == i
                sts64(addr, cvt_f16x2(w0.y, w0.x), cvt_f16x2(w1.y, w1.x));
                w0 = cmul(w0, rho0);
                w1 = cmul(w1, rho1);
            }
        }
    }
    __syncthreads();

    // ====== MMA phase: 8 warps = (mt 0..3) x (nh 0..1), m16 x n16 each ======
    const int wid = tx >> 5;
    const int lid = tx & 31;
    const int mt  = wid & 3;
    const int nh  = wid >> 2;

    float d[2][4];
#pragma unroll
    for (int nt = 0; nt < 2; nt++)
#pragma unroll
        for (int i = 0; i < 4; i++) d[nt][i] = 0.0f;

    const uint32_t lrow = (uint32_t)(lid & 15);
    const uint32_t c16  = (uint32_t)(lid & 16);      // k-half select (16B)
    const uint32_t swz  = (lrow & 7u) << 4;
    const uint32_t a_rowb = sbase + A_OFF + ((uint32_t)(mt * 16) + lrow) * 256u;
    const uint32_t b_rowb = sbase + B_OFF + ((uint32_t)(nh * 16) + lrow) * 256u;

#pragma unroll
    for (int kt = 0; kt < 8; kt++) {
        const uint32_t col = ((uint32_t)(kt * 32) + c16) ^ swz;
        uint32_t a[4], b[4];
        ldsm4(a, a_rowb + col);
        ldsm4(b, b_rowb + col);        // m0/m1: nt0/nt1 (k lo), m2/m3: (k hi)
        mma_f16(d[0], a, b[0], b[2]);
        mma_f16(d[1], a, b[1], b[3]);
    }

    // ================= Epilogue: D[c, j] -> out[h, 32c + j] =================
    float* outh = out + (size_t)h * SEQ_L;
    const int row = mt * 16 + (lid >> 2);            // c index (and row+8)
    const int jb  = nh * 16 + 2 * (lid & 3);         // j base
#pragma unroll
    for (int nt = 0; nt < 2; nt++) {
        *reinterpret_cast<float2*>(outh + 32 * row + jb + 8 * nt) =
            make_float2(d[nt][0], d[nt][1]);
        *reinterpret_cast<float2*>(outh + 32 * (row + 8) + jb + 8 * nt) =
            make_float2(d[nt][2], d[nt][3]);
    }
}

extern "C" void kernel_launch(void* const* d_in, const int* in_sizes, int n_in,
                              void* d_out, int out_size)
{
    const float* Cri   = (const float*)d_in[0];   // (1, H, N, 2)
    const float* logdt = (const float*)d_in[1];   // (H,)
    const float* Bri   = (const float*)d_in[2];   // (H, N, 2)  (n_ssm == H)
    const float* invAr = (const float*)d_in[3];   // (H, N)
    const float* Aim   = (const float*)d_in[4];   // (H, N)
    float* out = (float*)d_out;                   // (1, H, L)

    cudaFuncSetAttribute(ssk_hmma, cudaFuncAttributeMaxDynamicSharedMemorySize,
                         SMEM_BYTES);
    ssk_hmma<<<H_DIM, 256, SMEM_BYTES>>>(Cri, logdt, Bri, invAr, Aim, out);
}